// round 16
// baseline (speedup 1.0000x reference)
#include <cuda_runtime.h>
#include <cuda_fp16.h>
#include <math.h>
#include <stdint.h>

// Problem constants
#define CB   4
#define CL   2048
#define CDIN 512
#define CW   4096
#define CH   8
#define CDH  8
#define CDV  512
#define CNE  64
#define CM   (CB * CL)

#define SCALE_LOG2E 0.51012245933f

// Scale constants (exact powers of 2; folded into alpha, no extra rounding)
#define S_ACT 4096.0f
#define S_WT  256.0f

// ---------------------------------------------------------------------------
// Scratch (device globals; no cudaMalloc allowed)
// ---------------------------------------------------------------------------
__device__ float g_X [CM * CDIN];
__device__ float g_P [CM * CW];
__device__ float g_Q [CM * CNE];
__device__ float g_K [CM * CNE];
__device__ float g_DZ[CM * CDIN];
__device__ float g_PRJ[CM];

__device__ __half g_Xh[CM * CDIN], g_Xl[CM * CDIN];     // scale 1
__device__ __half g_Zh[CM * CW],   g_Zl[CM * CW];       // scale 4096
__device__ __half g_Vh[CM * CW],   g_Vl[CM * CW];       // scale 4096
__device__ __half g_Oh[CM * CW],   g_Ol[CM * CW];       // scale 4096
__device__ __half g_Ph[CM * CW],   g_Pl[CM * CW];       // scale 4096
__device__ __half g_Dwh[CW * CDIN], g_Dwl[CW * CDIN];   // D as [N=4096,K=512], x256
__device__ __half g_Dth[CDIN * CW], g_Dtl[CDIN * CW];   // D^T as [N=512,K=4096], x256
__device__ __half g_vwh[CW * CW],  g_vwl[CW * CW];      // x256
__device__ __half g_owh[CW * CW],  g_owl[CW * CW];      // x256
__device__ __half g_qwh[CNE * CW], g_qwl[CNE * CW];     // x256
__device__ __half g_kwh[CNE * CW], g_kwl[CNE * CW];     // x256

// ---------------------------------------------------------------------------
// Helpers
// ---------------------------------------------------------------------------
__device__ __forceinline__ uint32_t smem_u32(const void* p) {
    uint32_t a;
    asm("{ .reg .u64 t; cvta.to.shared.u64 t, %1; cvt.u32.u64 %0, t; }"
        : "=r"(a) : "l"(p));
    return a;
}

__device__ __forceinline__ void cpasync16(uint32_t dst, const void* src, unsigned sz) {
    asm volatile("cp.async.cg.shared.global [%0], [%1], 16, %2;"
                 :: "r"(dst), "l"(src), "r"(sz) : "memory");
}

__device__ __forceinline__ void mma16816(float* c, const uint32_t* a, const uint32_t* b) {
    asm volatile(
        "mma.sync.aligned.m16n8k16.row.col.f32.f16.f16.f32 "
        "{%0,%1,%2,%3}, {%4,%5,%6,%7}, {%8,%9}, {%0,%1,%2,%3};"
        : "+f"(c[0]), "+f"(c[1]), "+f"(c[2]), "+f"(c[3])
        : "r"(a[0]), "r"(a[1]), "r"(a[2]), "r"(a[3]), "r"(b[0]), "r"(b[1]));
}

__device__ __forceinline__ void ldm_x4(uint32_t* r, uint32_t addr) {
    asm volatile("ldmatrix.sync.aligned.m8n8.x4.shared.b16 {%0,%1,%2,%3}, [%4];"
                 : "=r"(r[0]), "=r"(r[1]), "=r"(r[2]), "=r"(r[3]) : "r"(addr));
}

__device__ __forceinline__ void ldm_x4_trans(uint32_t* r, uint32_t addr) {
    asm volatile("ldmatrix.sync.aligned.m8n8.x4.trans.shared.b16 {%0,%1,%2,%3}, [%4];"
                 : "=r"(r[0]), "=r"(r[1]), "=r"(r[2]), "=r"(r[3]) : "r"(addr));
}

__device__ __forceinline__ float ex2f(float x) {
    float r;
    asm("ex2.approx.ftz.f32 %0, %1;" : "=f"(r) : "f"(x));
    return r;
}

__device__ __forceinline__ void hsplit(float v, __half& h, __half& l) {
    h = __float2half_rn(v);
    l = __float2half_rn(v - __half2float(h));
}

// ---------------------------------------------------------------------------
// mma.sync double-fp16 GEMM.  C[8192, N] = epi( alpha * A[8192,K] @ B[N,K]^T )
//   PASSES==3: acc += Ah*Bh + Ah*Bl + Al*Bh   (~2^-22)
//   PASSES==2: acc += Ah*Bh + Ah*Bl           (~2^-12, big GEMMs only)
//   BM=128, 256 threads, __launch_bounds__(256,1) -> 255-reg budget.
//   3-stage cp.async pipeline + register double-buffered fragments:
//   step s+1's ldmatrix issues before step s's MMAs -> LDSM overlaps HMMA.
// ---------------------------------------------------------------------------
template<int BN, int PASSES>
__global__ __launch_bounds__(256, 1)
void mma_gemm(const __half* __restrict__ Ah, const __half* __restrict__ Al,
              const __half* __restrict__ Bh_, const __half* __restrict__ Bl_,
              const __half* __restrict__ B2h, const __half* __restrict__ B2l,
              int K, int N, int SH_in, int QK,
              float alpha, const float* __restrict__ bias_, const float* __restrict__ bias2,
              int relu,
              const float* __restrict__ addP, const float* __restrict__ proj,
              float* __restrict__ outF_, float* __restrict__ outF2,
              __half* __restrict__ outH, __half* __restrict__ outL, float oscale)
{
    constexpr int NT   = 256;
    constexpr int BM   = 128;
    constexpr int NF   = BN / 32;
    constexpr int ROWB = 144;
    constexpr int ASZ  = BM * ROWB;
    constexpr int BSZ  = BN * ROWB;
    constexpr int NA   = (PASSES == 3) ? 2 : 1;
    constexpr int OF_AH = 0, OF_AL = ASZ;
    constexpr int OF_BH = NA * ASZ, OF_BL = NA * ASZ + BSZ;
    constexpr int STAGE = NA * ASZ + 2 * BSZ;

    extern __shared__ __align__(16) char sm[];
    const uint32_t sbase = smem_u32(sm);

    const int tid = threadIdx.x;
    const int l   = tid & 31;
    const int wid = tid >> 5;
    const int wm  = (wid >> 2) * 64;
    const int wn  = (wid & 3) * (BN / 4);
    const int bm  = blockIdx.y * BM;

    int SH = SH_in;
    int bn;
    const __half* Bh = Bh_;
    const __half* Bl = Bl_;
    const float*  bias = bias_;
    float* outF = outF_;
    if (QK) {
        bn = 0;
        if (blockIdx.x == 1) { Bh = B2h; Bl = B2l; bias = bias2; outF = outF2; SH = 1; }
    } else {
        bn = blockIdx.x * BN;
    }

    float acc[4][NF][4];
    #pragma unroll
    for (int i = 0; i < 4; i++)
        #pragma unroll
        for (int j = 0; j < NF; j++)
            #pragma unroll
            for (int q = 0; q < 4; q++) acc[i][j][q] = 0.f;

    const int nch = K >> 6;

    auto stage = [&](int cc, int buf) {
        const int k0 = cc << 6;
        const uint32_t stg = sbase + buf * STAGE;
        #pragma unroll
        for (int i = 0; i < NA * BM * 8 / NT; i++) {
            int u   = tid + i * NT;
            int hl  = u / (BM * 8);
            int idx = u % (BM * 8);
            int row = idx >> 3, c16 = idx & 7;
            int gm  = bm + row;
            int rs; unsigned sz;
            if (SH) { bool ok = (gm & (CL - 1)) != 0; rs = ok ? gm - 1 : 0; sz = ok ? 16u : 0u; }
            else    { rs = gm; sz = 16u; }
            const __half* src = hl ? Al : Ah;
            cpasync16(stg + (hl ? OF_AL : OF_AH) + row * ROWB + c16 * 16,
                      src + (size_t)rs * K + k0 + c16 * 8, sz);
        }
        #pragma unroll
        for (int i = 0; i < 2 * BN * 8 / NT; i++) {
            int u   = tid + i * NT;
            int hl  = u / (BN * 8);
            int idx = u % (BN * 8);
            int row = idx >> 3, c16 = idx & 7;
            const __half* src = hl ? Bl : Bh;
            cpasync16(stg + (hl ? OF_BL : OF_BH) + row * ROWB + c16 * 16,
                      src + (size_t)(bn + row) * K + k0 + c16 * 8, 16u);
        }
        asm volatile("cp.async.commit_group;" ::: "memory");
    };

    const uint32_t aRowOff = (uint32_t)(wm + (l & 15)) * ROWB + ((l & 16) ? 16u : 0u);
    const uint32_t bRowOff = (uint32_t)(wn + (l & 7) + ((l & 16) ? 8 : 0)) * ROWB
                             + ((l & 8) ? 16u : 0u);

    stage(0, 0);
    if (nch > 1) stage(1, 1);

    // fragment double buffers (fits in the 255-reg budget from launch_bounds(256,1))
    uint32_t fah[2][4][4], fbh[2][NF][2], fbl[2][NF][2], fal[4][4];

    auto ldfr = [&](uint32_t stg, int s, int buf) {
        const uint32_t ks = (uint32_t)s * 32;
        #pragma unroll
        for (int p = 0; p < NF / 2; p++) {
            uint32_t ad = stg + bRowOff + (uint32_t)(p * 16) * ROWB + ks;
            ldm_x4(&fbh[buf][2 * p][0], ad + OF_BH);
            ldm_x4(&fbl[buf][2 * p][0], ad + OF_BL);
        }
        #pragma unroll
        for (int mf = 0; mf < 4; mf++)
            ldm_x4(fah[buf][mf], stg + OF_AH + aRowOff + (uint32_t)(mf * 16) * ROWB + ks);
    };

    for (int c = 0; c < nch; c++) {
        if (c + 1 < nch) asm volatile("cp.async.wait_group 1;" ::: "memory");
        else             asm volatile("cp.async.wait_group 0;" ::: "memory");
        __syncthreads();
        if (c + 2 < nch) stage(c + 2, (c + 2) % 3);

        const uint32_t stg = sbase + (uint32_t)(c % 3) * STAGE;
        ldfr(stg, 0, 0);
        #pragma unroll
        for (int s = 0; s < 4; s++) {
            const int cb = s & 1, nb = cb ^ 1;
            // just-in-time A-lo for this step (consumed by pass 3, far below)
            if (PASSES == 3) {
                #pragma unroll
                for (int mf = 0; mf < 4; mf++)
                    ldm_x4(fal[mf], stg + OF_AL + aRowOff
                                  + (uint32_t)(mf * 16) * ROWB + (uint32_t)s * 32);
            }
            // prefetch next step's fragments before this step's MMAs
            if (s < 3) ldfr(stg, s + 1, nb);

            #pragma unroll
            for (int mf = 0; mf < 4; mf++)
                #pragma unroll
                for (int nf = 0; nf < NF; nf++) mma16816(acc[mf][nf], fah[cb][mf], fbh[cb][nf]);
            #pragma unroll
            for (int mf = 0; mf < 4; mf++)
                #pragma unroll
                for (int nf = 0; nf < NF; nf++) mma16816(acc[mf][nf], fah[cb][mf], fbl[cb][nf]);
            if (PASSES == 3) {
                #pragma unroll
                for (int mf = 0; mf < 4; mf++)
                    #pragma unroll
                    for (int nf = 0; nf < NF; nf++) mma16816(acc[mf][nf], fal[mf], fbh[cb][nf]);
            }
        }
        __syncthreads();
    }

    // ---- epilogue ----
    const int r0 = bm + wm + (l >> 2);
    #pragma unroll
    for (int mf = 0; mf < 4; mf++) {
        int r = r0 + mf * 16;
        float pr0 = 0.f, pr1 = 0.f;
        if (addP) { pr0 = proj[r]; pr1 = proj[r + 8]; }
        #pragma unroll
        for (int nf = 0; nf < NF; nf++) {
            int col = bn + wn + nf * 8 + 2 * (l & 3);
            float v0 = acc[mf][nf][0] * alpha, v1 = acc[mf][nf][1] * alpha;
            float v2 = acc[mf][nf][2] * alpha, v3 = acc[mf][nf][3] * alpha;
            if (bias) {
                float b0 = bias[col], b1 = bias[col + 1];
                v0 += b0; v1 += b1; v2 += b0; v3 += b1;
            }
            if (relu) {
                v0 = fmaxf(v0, 0.f); v1 = fmaxf(v1, 0.f);
                v2 = fmaxf(v2, 0.f); v3 = fmaxf(v3, 0.f);
            }
            if (addP) {
                float2 p0 = *(const float2*)(addP + (size_t)r * N + col);
                float2 p1 = *(const float2*)(addP + (size_t)(r + 8) * N + col);
                v0 += p0.x * pr0; v1 += p0.y * pr0;
                v2 += p1.x * pr1; v3 += p1.y * pr1;
            }
            if (outF) {
                *(float2*)(outF + (size_t)r * N + col)       = make_float2(v0, v1);
                *(float2*)(outF + (size_t)(r + 8) * N + col) = make_float2(v2, v3);
            }
            if (outH) {
                union { __half b[2]; uint32_t u; } h0, l0, h1, l1;
                hsplit(v0 * oscale, h0.b[0], l0.b[0]); hsplit(v1 * oscale, h0.b[1], l0.b[1]);
                hsplit(v2 * oscale, h1.b[0], l1.b[0]); hsplit(v3 * oscale, h1.b[1], l1.b[1]);
                *(uint32_t*)(outH + (size_t)r * N + col)       = h0.u;
                *(uint32_t*)(outL + (size_t)r * N + col)       = l0.u;
                *(uint32_t*)(outH + (size_t)(r + 8) * N + col) = h1.u;
                *(uint32_t*)(outL + (size_t)(r + 8) * N + col) = l1.u;
            }
        }
    }
}

// ---------------------------------------------------------------------------
// Weight / input conversion kernels (fp16 hi/lo with scale)
// ---------------------------------------------------------------------------
__global__ __launch_bounds__(256)
void conv_split(const float* __restrict__ in,
                __half* __restrict__ hi, __half* __restrict__ lo, float scale)
{
    int i = blockIdx.x * 256 + threadIdx.x;
    float4 v = ((const float4*)in)[i];
    union { __half b[4]; uint2 u; } uh, ul;
    hsplit(v.x * scale, uh.b[0], ul.b[0]);
    hsplit(v.y * scale, uh.b[1], ul.b[1]);
    hsplit(v.z * scale, uh.b[2], ul.b[2]);
    hsplit(v.w * scale, uh.b[3], ul.b[3]);
    ((uint2*)hi)[i] = uh.u;
    ((uint2*)lo)[i] = ul.u;
}

__global__ __launch_bounds__(256)
void conv_trans(const float* __restrict__ D,
                __half* __restrict__ th, __half* __restrict__ tl, float scale)
{
    __shared__ float t[32][33];
    const int n0 = blockIdx.x * 32, k0 = blockIdx.y * 32;
    const int tx = threadIdx.x & 31, ty = threadIdx.x >> 5;
    #pragma unroll
    for (int j = 0; j < 32; j += 8)
        t[ty + j][tx] = D[(size_t)(k0 + ty + j) * CDIN + n0 + tx];
    __syncthreads();
    #pragma unroll
    for (int j = 0; j < 32; j += 8) {
        float v = t[tx][ty + j] * scale;
        __half h, l; hsplit(v, h, l);
        th[(size_t)(n0 + ty + j) * CW + k0 + tx] = h;
        tl[(size_t)(n0 + ty + j) * CW + k0 + tx] = l;
    }
}

__global__ __launch_bounds__(256)
void subb_kernel(const float* __restrict__ xin, const float* __restrict__ b,
                 float* __restrict__ X,
                 __half* __restrict__ Xh, __half* __restrict__ Xl)
{
    int i = blockIdx.x * 256 + threadIdx.x;
    float4 v = ((const float4*)xin)[i];
    int col = (i * 4) & (CDIN - 1);
    float4 bb = *(const float4*)(b + col);
    v.x -= bb.x; v.y -= bb.y; v.z -= bb.z; v.w -= bb.w;
    ((float4*)X)[i] = v;
    union { __half b[4]; uint2 u; } uh, ul;
    hsplit(v.x, uh.b[0], ul.b[0]);
    hsplit(v.y, uh.b[1], ul.b[1]);
    hsplit(v.z, uh.b[2], ul.b[2]);
    hsplit(v.w, uh.b[3], ul.b[3]);
    ((uint2*)Xh)[i] = uh.u;
    ((uint2*)Xl)[i] = ul.u;
}

// ---------------------------------------------------------------------------
// Causal attention: fp32 scores/softmax, tensor-core P@V (3-pass fp16 hi/lo).
// Block = 64 q-rows x 256 dv (dvt in {0,1}), 256 threads, 8 warps (4q x 2dv).
// qt REVERSED: heavy (large-qt) blocks dispatch first -> light tail wave.
// ---------------------------------------------------------------------------
__global__ __launch_bounds__(256)
void attn_kernel(const float* __restrict__ Q, const float* __restrict__ Kt,
                 const __half* __restrict__ Vh, const __half* __restrict__ Vl,
                 __half* __restrict__ Oh, __half* __restrict__ Ol)
{
    __shared__ float qs[64][8];
    __shared__ float ks[32][8];
    __shared__ __align__(16) __half pH[64][40];    // 80B row stride
    __shared__ __align__(16) __half pL[64][40];
    __shared__ __align__(16) __half vsh[32][264];  // 528B row stride
    __shared__ __align__(16) __half vsl[32][264];
    __shared__ float rowM[64], rowL[64], rowF[64];

    const int tid = threadIdx.x;
    const int dvt = blockIdx.x;          // 0..1 (256 dv each)
    const int qt  = (int)(gridDim.y - 1 - blockIdx.y);   // reversed: heavy first
    const int bh  = blockIdx.z;          // 0..31
    const int bb  = bh >> 3, h = bh & 7;
    const int qBase = qt * 64;

    #pragma unroll
    for (int i = 0; i < 2; i++) {
        int idx = tid + i * 256;
        qs[idx >> 3][idx & 7] =
            Q[(size_t)(bb * CL + qBase + (idx >> 3)) * CNE + h * CDH + (idx & 7)];
    }
    if (tid < 64) { rowM[tid] = -INFINITY; rowL[tid] = 0.f; }

    const int l   = tid & 31, wid = tid >> 5;
    const int wq  = (wid >> 1) * 16;     // 0,16,32,48
    const int wd  = (wid & 1) * 128;     // 0,128

    float acc[16][4];
    #pragma unroll
    for (int nf = 0; nf < 16; nf++)
        #pragma unroll
        for (int q = 0; q < 4; q++) acc[nf][q] = 0.f;

    const int sr = tid >> 2, sg = tid & 3;

    const uint32_t pH0 = smem_u32(pH), pL0 = smem_u32(pL);
    const uint32_t vh0 = smem_u32(vsh), vl0 = smem_u32(vsl);
    const uint32_t aOff  = (uint32_t)(wq + (l & 15)) * 80 + ((l & 16) ? 16u : 0u);
    const uint32_t vRow  = (uint32_t)(l & 15);
    const uint32_t vCol8 = (uint32_t)(l >> 4) * 8;

    const int nst = qt * 2 + 2;
    for (int st = 0; st < nst; st++) {
        const int s0 = st * 32;
        __syncthreads();
        ks[tid >> 3][tid & 7] =
            Kt[(size_t)(bb * CL + s0 + (tid >> 3)) * CNE + h * CDH + (tid & 7)];
        // V tile: 32 rows x 256 halves, hi+lo
        #pragma unroll
        for (int i = 0; i < 4; i++) {
            int idx = tid + i * 256;             // 0..1023
            int r = idx >> 5, c8 = (idx & 31) * 8;
            size_t g = (size_t)(bb * CL + s0 + r) * CW + h * CDV + dvt * 256 + c8;
            *(uint4*)&vsh[r][c8] = *(const uint4*)(Vh + g);
            *(uint4*)&vsl[r][c8] = *(const uint4*)(Vl + g);
        }
        __syncthreads();

        // scores + online softmax: thread (sr, sg) owns row sr, s = sg*8..+7
        {
            float qv[8];
            #pragma unroll
            for (int d = 0; d < 8; d++) qv[d] = qs[sr][d];
            const int lglob = qBase + sr;
            float sc[8];
            #pragma unroll
            for (int i = 0; i < 8; i++) {
                int s = sg * 8 + i;
                float dot = 0.f;
                #pragma unroll
                for (int d = 0; d < 8; d++) dot += qv[d] * ks[s][d];
                sc[i] = (s0 + s <= lglob) ? dot * SCALE_LOG2E : -INFINITY;
            }
            float mt = sc[0];
            #pragma unroll
            for (int i = 1; i < 8; i++) mt = fmaxf(mt, sc[i]);
            mt = fmaxf(mt, __shfl_xor_sync(0xffffffffu, mt, 1));
            mt = fmaxf(mt, __shfl_xor_sync(0xffffffffu, mt, 2));
            const float mold = rowM[sr];
            const float mnew = fmaxf(mold, mt);
            float p[8], lsum = 0.f;
            #pragma unroll
            for (int i = 0; i < 8; i++) { p[i] = ex2f(sc[i] - mnew); lsum += p[i]; }
            lsum += __shfl_xor_sync(0xffffffffu, lsum, 1);
            lsum += __shfl_xor_sync(0xffffffffu, lsum, 2);
            if (sg == 0) {
                float f = ex2f(mold - mnew);
                rowF[sr] = f;
                rowL[sr] = rowL[sr] * f + lsum;
                rowM[sr] = mnew;
            }
            union { __half b[8]; uint4 u; } uh, ul;
            #pragma unroll
            for (int i = 0; i < 8; i++) hsplit(p[i], uh.b[i], ul.b[i]);
            *(uint4*)&pH[sr][sg * 8] = uh.u;
            *(uint4*)&pL[sr][sg * 8] = ul.u;
        }
        __syncthreads();

        // rescale accumulators
        const float f0 = rowF[wq + (l >> 2)], f1 = rowF[wq + 8 + (l >> 2)];
        #pragma unroll
        for (int nf = 0; nf < 16; nf++) {
            acc[nf][0] *= f0; acc[nf][1] *= f0;
            acc[nf][2] *= f1; acc[nf][3] *= f1;
        }

        // P fragments (hi/lo, 2 k16-steps)
        uint32_t aH[2][4], aL[2][4];
        ldm_x4(aH[0], pH0 + aOff);
        ldm_x4(aH[1], pH0 + aOff + 32);
        ldm_x4(aL[0], pL0 + aOff);
        ldm_x4(aL[1], pL0 + aOff + 32);

        #pragma unroll
        for (int kk = 0; kk < 2; kk++) {
            #pragma unroll
            for (int nb = 0; nb < 8; nb++) {
                uint32_t ad = (uint32_t)((kk * 16 + vRow) * 528)
                            + (uint32_t)((wd + nb * 16) + vCol8) * 2;
                uint32_t bv[4], blo[4];
                ldm_x4_trans(bv,  vh0 + ad);
                ldm_x4_trans(blo, vl0 + ad);
                mma16816(acc[2 * nb],     aH[kk], &bv[0]);
                mma16816(acc[2 * nb + 1], aH[kk], &bv[2]);
                mma16816(acc[2 * nb],     aL[kk], &bv[0]);
                mma16816(acc[2 * nb + 1], aL[kk], &bv[2]);
                mma16816(acc[2 * nb],     aH[kk], &blo[0]);
                mma16816(acc[2 * nb + 1], aH[kk], &blo[2]);
            }
        }
    }

    // epilogue: O_scaled = acc / rowL (acc already carries x4096 via V)
    const int r0 = wq + (l >> 2);
    const float inv0 = 1.f / rowL[r0], inv1 = 1.f / rowL[r0 + 8];
    #pragma unroll
    for (int nf = 0; nf < 16; nf++) {
        int col = h * CDV + dvt * 256 + wd + nf * 8 + 2 * (l & 3);
        size_t g0 = (size_t)(bb * CL + qBase + r0) * CW + col;
        size_t g1 = (size_t)(bb * CL + qBase + r0 + 8) * CW + col;
        union { __half b[2]; uint32_t u; } h0, l0_, h1, l1_;
        hsplit(acc[nf][0] * inv0, h0.b[0], l0_.b[0]);
        hsplit(acc[nf][1] * inv0, h0.b[1], l0_.b[1]);
        hsplit(acc[nf][2] * inv1, h1.b[0], l1_.b[0]);
        hsplit(acc[nf][3] * inv1, h1.b[1], l1_.b[1]);
        *(uint32_t*)(Oh + g0) = h0.u; *(uint32_t*)(Ol + g0) = l0_.u;
        *(uint32_t*)(Oh + g1) = h1.u; *(uint32_t*)(Ol + g1) = l1_.u;
    }
}

// ---------------------------------------------------------------------------
// proj = <Dz,x>/(||Dz||+eps)^2 ; x2 = x - proj*Dz -> fp16 hi/lo (scale 1)
// ---------------------------------------------------------------------------
__global__ __launch_bounds__(256)
void proj_kernel(const float* __restrict__ DZ, const float* __restrict__ X,
                 float* __restrict__ proj,
                 __half* __restrict__ Xh, __half* __restrict__ Xl)
{
    __shared__ float sn[8], sd[8], s_ps;
    const int m = blockIdx.x;
    const int tid = threadIdx.x;
    const float* dz = DZ + (size_t)m * CDIN;
    const float* x  = X  + (size_t)m * CDIN;

    float dzv[2], xv[2];
    float n2 = 0.f, dt = 0.f;
    #pragma unroll
    for (int i = 0; i < 2; i++) {
        int c = tid + i * 256;
        dzv[i] = dz[c];
        xv[i]  = x[c];
        n2 += dzv[i] * dzv[i];
        dt += dzv[i] * xv[i];
    }
    #pragma unroll
    for (int o = 16; o; o >>= 1) {
        n2 += __shfl_xor_sync(0xffffffffu, n2, o);
        dt += __shfl_xor_sync(0xffffffffu, dt, o);
    }
    int w = tid >> 5;
    if ((tid & 31) == 0) { sn[w] = n2; sd[w] = dt; }
    __syncthreads();
    if (tid == 0) {
        float N2 = 0.f, DT = 0.f;
        #pragma unroll
        for (int i = 0; i < 8; i++) { N2 += sn[i]; DT += sd[i]; }
        float nrm = sqrtf(N2) + 1e-6f;
        float ps  = DT / (nrm * nrm);
        s_ps = ps;
        proj[m] = ps;
    }
    __syncthreads();
    float ps = s_ps;
    #pragma unroll
    for (int i = 0; i < 2; i++) {
        int c = tid + i * 256;
        float v = xv[i] - ps * dzv[i];
        __half h, l; hsplit(v, h, l);
        Xh[(size_t)m * CDIN + c] = h;
        Xl[(size_t)m * CDIN + c] = l;
    }
}

// ---------------------------------------------------------------------------
// launch  (ordered so ncu -s 5 -c 1 profiles the big v-GEMM)
// ---------------------------------------------------------------------------
extern "C" void kernel_launch(void* const* d_in, const int* in_sizes, int n_in,
                              void* d_out, int out_size)
{
    const float* x_input = (const float*)d_in[0];
    const float* D    = (const float*)d_in[1];
    const float* b    = (const float*)d_in[2];
    const float* k_w  = (const float*)d_in[3];
    const float* k_b  = (const float*)d_in[4];
    const float* q_w  = (const float*)d_in[5];
    const float* q_b  = (const float*)d_in[6];
    const float* v_w  = (const float*)d_in[7];
    const float* v_b  = (const float*)d_in[8];
    const float* o_w  = (const float*)d_in[9];
    const float* o_b  = (const float*)d_in[10];
    float* out = (float*)d_out;

    float *X, *P, *Q, *K, *DZ, *PRJ;
    __half *Xh, *Xl, *Zh, *Zl, *Vh, *Vl, *Oh, *Ol, *Ph, *Pl;
    __half *Dwh, *Dwl, *Dth, *Dtl, *vwh, *vwl, *owh, *owl, *qwh, *qwl, *kwh, *kwl;
    cudaGetSymbolAddress((void**)&X,  g_X);
    cudaGetSymbolAddress((void**)&P,  g_P);
    cudaGetSymbolAddress((void**)&Q,  g_Q);
    cudaGetSymbolAddress((void**)&K,  g_K);
    cudaGetSymbolAddress((void**)&DZ, g_DZ);
    cudaGetSymbolAddress((void**)&PRJ, g_PRJ);
    cudaGetSymbolAddress((void**)&Xh, g_Xh); cudaGetSymbolAddress((void**)&Xl, g_Xl);
    cudaGetSymbolAddress((void**)&Zh, g_Zh); cudaGetSymbolAddress((void**)&Zl, g_Zl);
    cudaGetSymbolAddress((void**)&Vh, g_Vh); cudaGetSymbolAddress((void**)&Vl, g_Vl);
    cudaGetSymbolAddress((void**)&Oh, g_Oh); cudaGetSymbolAddress((void**)&Ol, g_Ol);
    cudaGetSymbolAddress((void**)&Ph, g_Ph); cudaGetSymbolAddress((void**)&Pl, g_Pl);
    cudaGetSymbolAddress((void**)&Dwh, g_Dwh); cudaGetSymbolAddress((void**)&Dwl, g_Dwl);
    cudaGetSymbolAddress((void**)&Dth, g_Dth); cudaGetSymbolAddress((void**)&Dtl, g_Dtl);
    cudaGetSymbolAddress((void**)&vwh, g_vwh); cudaGetSymbolAddress((void**)&vwl, g_vwl);
    cudaGetSymbolAddress((void**)&owh, g_owh); cudaGetSymbolAddress((void**)&owl, g_owl);
    cudaGetSymbolAddress((void**)&qwh, g_qwh); cudaGetSymbolAddress((void**)&qwl, g_qwl);
    cudaGetSymbolAddress((void**)&kwh, g_kwh); cudaGetSymbolAddress((void**)&kwl, g_kwl);

    const int SM_3  = 3 * (2 * 128 * 144 + 2 * 128 * 144);   // <128,3>: 221184
    const int SM_2  = 3 * (1 * 128 * 144 + 2 * 128 * 144);   // <128,2>: 165888
    const int SM_Q  = 3 * (2 * 128 * 144 + 2 * 64 * 144);    // <64,3>:  165888
    cudaFuncSetAttribute(mma_gemm<128, 3>, cudaFuncAttributeMaxDynamicSharedMemorySize, SM_3);
    cudaFuncSetAttribute(mma_gemm<128, 2>, cudaFuncAttributeMaxDynamicSharedMemorySize, SM_2);
    cudaFuncSetAttribute(mma_gemm<64, 3>,  cudaFuncAttributeMaxDynamicSharedMemorySize, SM_Q);

    const float lam = 1.0f / (4.0f * CDIN);
    const float iAW = 1.0f / (S_ACT * S_WT);   // 2^-20, exact
    dim3 blk(256);

    // [0] [1] D conversions, [2] subb
    conv_split<<<(CW * CDIN) / 1024, blk>>>(D, Dwh, Dwl, S_WT);
    conv_trans<<<dim3(CDIN / 32, CW / 32), blk>>>(D, Dth, Dtl, S_WT);
    subb_kernel<<<(CM * CDIN) / 1024, blk>>>(x_input, b, X, Xh, Xl);

    // [3] z_input = relu(lam * x @ D^T)
    mma_gemm<128, 3><<<dim3(CW / 128, CM / 128), 256, SM_3>>>(
        Xh, Xl, Dwh, Dwl, nullptr, nullptr, CDIN, CW, 0, 0,
        lam / S_WT, nullptr, nullptr, 1, nullptr, nullptr,
        nullptr, nullptr, Zh, Zl, S_ACT);

    // [4] v_w conversion, [5] v GEMM (ncu profile target) -> Vh/Vl (x4096)
    conv_split<<<(CW * CW) / 1024, blk>>>(v_w, vwh, vwl, S_WT);
    mma_gemm<128, 2><<<dim3(CW / 128, CM / 128), 256, SM_2>>>(
        Zh, Zl, vwh, vwl, nullptr, nullptr, CW, CW, 1, 0,
        iAW, v_b, nullptr, 0, nullptr, nullptr,
        nullptr, nullptr, Vh, Vl, S_ACT);

    // [6] [7] q/k conversions, [8] fused q&k GEMM
    conv_split<<<(CNE * CW) / 1024, blk>>>(q_w, qwh, qwl, S_WT);
    conv_split<<<(CNE * CW) / 1024, blk>>>(k_w, kwh, kwl, S_WT);
    mma_gemm<64, 3><<<dim3(2, CM / 128), 256, SM_Q>>>(
        Zh, Zl, qwh, qwl, kwh, kwl, CW, CNE, 0, 1,
        iAW, q_b, k_b, 0, nullptr, nullptr,
        Q, K, nullptr, nullptr, 1.f);

    // [9] attention (tensor-core P@V, heavy-first scheduling)
    attn_kernel<<<dim3(2, CL / 64, CB * CH), blk>>>(Q, K, Vh, Vl, Oh, Ol);

    // [10] o_w conversion, [11] z_pred_ = relu(o @ o_w^T + o_b)
    conv_split<<<(CW * CW) / 1024, blk>>>(o_w, owh, owl, S_WT);
    mma_gemm<128, 2><<<dim3(CW / 128, CM / 128), 256, SM_2>>>(
        Oh, Ol, owh, owl, nullptr, nullptr, CW, CW, 0, 0,
        iAW, o_b, nullptr, 1, nullptr, nullptr,
        P, nullptr, Ph, Pl, S_ACT);

    // [12] Dz = z_pred_ @ D
    mma_gemm<128, 3><<<dim3(CDIN / 128, CM / 128), 256, SM_3>>>(
        Ph, Pl, Dth, Dtl, nullptr, nullptr, CW, CDIN, 0, 0,
        iAW, nullptr, nullptr, 0, nullptr, nullptr,
        DZ, nullptr, nullptr, nullptr, 1.f);

    // [13] proj scale + x2
    proj_kernel<<<CM, blk>>>(DZ, X, PRJ, Xh, Xl);

    // [14] z_sum = relu(lam * x2 @ D^T) + z_pred_ * proj
    mma_gemm<128, 3><<<dim3(CW / 128, CM / 128), 256, SM_3>>>(
        Xh, Xl, Dwh, Dwl, nullptr, nullptr, CDIN, CW, 0, 0,
        lam / S_WT, nullptr, nullptr, 1, P, PRJ,
        nullptr, nullptr, Zh, Zl, S_ACT);

    // [15] x_recons = z_sum @ D + b
    mma_gemm<128, 3><<<dim3(CDIN / 128, CM / 128), 256, SM_3>>>(
        Zh, Zl, Dth, Dtl, nullptr, nullptr, CW, CDIN, 0, 0,
        iAW, b, nullptr, 0, nullptr, nullptr,
        out, nullptr, nullptr, nullptr, 1.f);
}

// round 17
// speedup vs baseline: 1.3435x; 1.3435x over previous
#include <cuda_runtime.h>
#include <cuda_fp16.h>
#include <math.h>
#include <stdint.h>

// Problem constants
#define CB   4
#define CL   2048
#define CDIN 512
#define CW   4096
#define CH   8
#define CDH  8
#define CDV  512
#define CNE  64
#define CM   (CB * CL)

#define SCALE_LOG2E 0.51012245933f

// Scale constants (exact powers of 2; folded into alpha, no extra rounding)
#define S_ACT 4096.0f
#define S_WT  256.0f

// ---------------------------------------------------------------------------
// Scratch (device globals; no cudaMalloc allowed)
// ---------------------------------------------------------------------------
__device__ float g_X [CM * CDIN];
__device__ float g_P [CM * CW];
__device__ float g_Q [CM * CNE];
__device__ float g_K [CM * CNE];
__device__ float g_DZ[CM * CDIN];
__device__ float g_PRJ[CM];

__device__ __half g_Xh[CM * CDIN], g_Xl[CM * CDIN];     // scale 1
__device__ __half g_Zh[CM * CW],   g_Zl[CM * CW];       // scale 4096
__device__ __half g_Vh[CM * CW],   g_Vl[CM * CW];       // scale 4096
__device__ __half g_Oh[CM * CW],   g_Ol[CM * CW];       // scale 4096
__device__ __half g_Ph[CM * CW],   g_Pl[CM * CW];       // scale 4096
__device__ __half g_Dwh[CW * CDIN], g_Dwl[CW * CDIN];   // D as [N=4096,K=512], x256
__device__ __half g_Dth[CDIN * CW], g_Dtl[CDIN * CW];   // D^T as [N=512,K=4096], x256
__device__ __half g_vwh[CW * CW],  g_vwl[CW * CW];      // x256
__device__ __half g_owh[CW * CW],  g_owl[CW * CW];      // x256
__device__ __half g_qwh[CNE * CW], g_qwl[CNE * CW];     // x256
__device__ __half g_kwh[CNE * CW], g_kwl[CNE * CW];     // x256

// ---------------------------------------------------------------------------
// Helpers
// ---------------------------------------------------------------------------
__device__ __forceinline__ uint32_t smem_u32(const void* p) {
    uint32_t a;
    asm("{ .reg .u64 t; cvta.to.shared.u64 t, %1; cvt.u32.u64 %0, t; }"
        : "=r"(a) : "l"(p));
    return a;
}

__device__ __forceinline__ void cpasync16(uint32_t dst, const void* src, unsigned sz) {
    asm volatile("cp.async.cg.shared.global [%0], [%1], 16, %2;"
                 :: "r"(dst), "l"(src), "r"(sz) : "memory");
}

__device__ __forceinline__ void mma16816(float* c, const uint32_t* a, const uint32_t* b) {
    asm volatile(
        "mma.sync.aligned.m16n8k16.row.col.f32.f16.f16.f32 "
        "{%0,%1,%2,%3}, {%4,%5,%6,%7}, {%8,%9}, {%0,%1,%2,%3};"
        : "+f"(c[0]), "+f"(c[1]), "+f"(c[2]), "+f"(c[3])
        : "r"(a[0]), "r"(a[1]), "r"(a[2]), "r"(a[3]), "r"(b[0]), "r"(b[1]));
}

__device__ __forceinline__ void ldm_x4(uint32_t* r, uint32_t addr) {
    asm volatile("ldmatrix.sync.aligned.m8n8.x4.shared.b16 {%0,%1,%2,%3}, [%4];"
                 : "=r"(r[0]), "=r"(r[1]), "=r"(r[2]), "=r"(r[3]) : "r"(addr));
}

__device__ __forceinline__ void ldm_x4_trans(uint32_t* r, uint32_t addr) {
    asm volatile("ldmatrix.sync.aligned.m8n8.x4.trans.shared.b16 {%0,%1,%2,%3}, [%4];"
                 : "=r"(r[0]), "=r"(r[1]), "=r"(r[2]), "=r"(r[3]) : "r"(addr));
}

__device__ __forceinline__ float ex2f(float x) {
    float r;
    asm("ex2.approx.ftz.f32 %0, %1;" : "=f"(r) : "f"(x));
    return r;
}

__device__ __forceinline__ void hsplit(float v, __half& h, __half& l) {
    h = __float2half_rn(v);
    l = __float2half_rn(v - __half2float(h));
}

// ---------------------------------------------------------------------------
// mma.sync double-fp16 GEMM.  C[8192, N] = epi( alpha * A[8192,K] @ B[N,K]^T )
//   PASSES==3: acc += Ah*Bh + Ah*Bl + Al*Bh   (~2^-22)
//   PASSES==2: acc += Ah*Bh + Ah*Bl           (~2^-12)
//   PASSES==1: acc += Ah*Bh                   (~2^-11, giants only)
//   BM=128 -> 256 threads; BM=256 -> 512 threads (4 warps/SMSP).
//   NSTG auto: 3-stage if it fits in 228KB smem, else 2-stage
//   (2-stage issues stage c+1 BEFORE waiting on c -> copy overlaps compute).
// ---------------------------------------------------------------------------
template<int BM, int BN, int PASSES>
__global__ __launch_bounds__((BM == 256) ? 512 : 256)
void mma_gemm(const __half* __restrict__ Ah, const __half* __restrict__ Al,
              const __half* __restrict__ Bh_, const __half* __restrict__ Bl_,
              const __half* __restrict__ B2h, const __half* __restrict__ B2l,
              int K, int N, int SH_in, int QK,
              float alpha, const float* __restrict__ bias_, const float* __restrict__ bias2,
              int relu,
              const float* __restrict__ addP, const float* __restrict__ proj,
              float* __restrict__ outF_, float* __restrict__ outF2,
              __half* __restrict__ outH, __half* __restrict__ outL, float oscale)
{
    constexpr int NT   = (BM == 256) ? 512 : 256;
    constexpr int NF   = BN / 32;
    constexpr int ROWB = 144;
    constexpr int ASZ  = BM * ROWB;
    constexpr int BSZ  = BN * ROWB;
    constexpr int NA   = (PASSES == 3) ? 2 : 1;   // A tensors staged
    constexpr int NB   = (PASSES >= 2) ? 2 : 1;   // B tensors staged
    constexpr int OF_AH = 0, OF_AL = ASZ;
    constexpr int OF_BH = NA * ASZ, OF_BL = NA * ASZ + BSZ;
    constexpr int STAGE = NA * ASZ + NB * BSZ;
    constexpr int NSTG  = (3 * STAGE <= 225 * 1024) ? 3 : 2;

    extern __shared__ __align__(16) char sm[];
    const uint32_t sbase = smem_u32(sm);

    const int tid = threadIdx.x;
    const int l   = tid & 31;
    const int wid = tid >> 5;
    const int wm  = (wid >> 2) * 64;
    const int wn  = (wid & 3) * (BN / 4);
    const int bm  = blockIdx.y * BM;

    int SH = SH_in;
    int bn;
    const __half* Bh = Bh_;
    const __half* Bl = Bl_;
    const float*  bias = bias_;
    float* outF = outF_;
    if (QK) {
        bn = 0;
        if (blockIdx.x == 1) { Bh = B2h; Bl = B2l; bias = bias2; outF = outF2; SH = 1; }
    } else {
        bn = blockIdx.x * BN;
    }

    float acc[4][NF][4];
    #pragma unroll
    for (int i = 0; i < 4; i++)
        #pragma unroll
        for (int j = 0; j < NF; j++)
            #pragma unroll
            for (int q = 0; q < 4; q++) acc[i][j][q] = 0.f;

    const int nch = K >> 6;

    auto stage = [&](int cc, int buf) {
        const int k0 = cc << 6;
        const uint32_t stg = sbase + buf * STAGE;
        #pragma unroll
        for (int i = 0; i < NA * BM * 8 / NT; i++) {
            int u   = tid + i * NT;
            int hl  = u / (BM * 8);
            int idx = u % (BM * 8);
            int row = idx >> 3, c16 = idx & 7;
            int gm  = bm + row;
            int rs; unsigned sz;
            if (SH) { bool ok = (gm & (CL - 1)) != 0; rs = ok ? gm - 1 : 0; sz = ok ? 16u : 0u; }
            else    { rs = gm; sz = 16u; }
            const __half* src = hl ? Al : Ah;
            cpasync16(stg + (hl ? OF_AL : OF_AH) + row * ROWB + c16 * 16,
                      src + (size_t)rs * K + k0 + c16 * 8, sz);
        }
        #pragma unroll
        for (int i = 0; i < NB * BN * 8 / NT; i++) {
            int u   = tid + i * NT;
            int hl  = u / (BN * 8);
            int idx = u % (BN * 8);
            int row = idx >> 3, c16 = idx & 7;
            const __half* src = hl ? Bl : Bh;
            cpasync16(stg + (hl ? OF_BL : OF_BH) + row * ROWB + c16 * 16,
                      src + (size_t)(bn + row) * K + k0 + c16 * 8, 16u);
        }
        asm volatile("cp.async.commit_group;" ::: "memory");
    };

    const uint32_t aRowOff = (uint32_t)(wm + (l & 15)) * ROWB + ((l & 16) ? 16u : 0u);
    const uint32_t bRowOff = (uint32_t)(wn + (l & 7) + ((l & 16) ? 8 : 0)) * ROWB
                             + ((l & 8) ? 16u : 0u);

    stage(0, 0);
    if (NSTG == 3 && nch > 1) stage(1, 1);

    for (int c = 0; c < nch; c++) {
        if (NSTG == 2 && c + 1 < nch) stage(c + 1, (c + 1) & 1);
        if (c + 1 < nch) asm volatile("cp.async.wait_group 1;" ::: "memory");
        else             asm volatile("cp.async.wait_group 0;" ::: "memory");
        __syncthreads();
        if (NSTG == 3 && c + 2 < nch) stage(c + 2, (c + 2) % 3);

        const uint32_t stg = sbase + (uint32_t)(c % NSTG) * STAGE;
        #pragma unroll
        for (int s = 0; s < 4; s++) {
            const uint32_t ks = s * 32;
            uint32_t bh[NF][2], bl[NF][2];
            #pragma unroll
            for (int p = 0; p < NF / 2; p++) {
                uint32_t ad = stg + bRowOff + (uint32_t)(p * 16) * ROWB + ks;
                ldm_x4(&bh[2 * p][0], ad + OF_BH);
                if (PASSES >= 2) ldm_x4(&bl[2 * p][0], ad + OF_BL);
            }
            uint32_t af[4][4];
            #pragma unroll
            for (int mf = 0; mf < 4; mf++)
                ldm_x4(af[mf], stg + OF_AH + aRowOff + (uint32_t)(mf * 16) * ROWB + ks);
            #pragma unroll
            for (int mf = 0; mf < 4; mf++)
                #pragma unroll
                for (int nf = 0; nf < NF; nf++) mma16816(acc[mf][nf], af[mf], bh[nf]);
            if (PASSES >= 2) {
                #pragma unroll
                for (int mf = 0; mf < 4; mf++)
                    #pragma unroll
                    for (int nf = 0; nf < NF; nf++) mma16816(acc[mf][nf], af[mf], bl[nf]);
            }
            if (PASSES == 3) {
                #pragma unroll
                for (int mf = 0; mf < 4; mf++)
                    ldm_x4(af[mf], stg + OF_AL + aRowOff + (uint32_t)(mf * 16) * ROWB + ks);
                #pragma unroll
                for (int mf = 0; mf < 4; mf++)
                    #pragma unroll
                    for (int nf = 0; nf < NF; nf++) mma16816(acc[mf][nf], af[mf], bh[nf]);
            }
        }
        __syncthreads();
    }

    // ---- epilogue ----
    const int r0 = bm + wm + (l >> 2);
    #pragma unroll
    for (int mf = 0; mf < 4; mf++) {
        int r = r0 + mf * 16;
        float pr0 = 0.f, pr1 = 0.f;
        if (addP) { pr0 = proj[r]; pr1 = proj[r + 8]; }
        #pragma unroll
        for (int nf = 0; nf < NF; nf++) {
            int col = bn + wn + nf * 8 + 2 * (l & 3);
            float v0 = acc[mf][nf][0] * alpha, v1 = acc[mf][nf][1] * alpha;
            float v2 = acc[mf][nf][2] * alpha, v3 = acc[mf][nf][3] * alpha;
            if (bias) {
                float b0 = bias[col], b1 = bias[col + 1];
                v0 += b0; v1 += b1; v2 += b0; v3 += b1;
            }
            if (relu) {
                v0 = fmaxf(v0, 0.f); v1 = fmaxf(v1, 0.f);
                v2 = fmaxf(v2, 0.f); v3 = fmaxf(v3, 0.f);
            }
            if (addP) {
                float2 p0 = *(const float2*)(addP + (size_t)r * N + col);
                float2 p1 = *(const float2*)(addP + (size_t)(r + 8) * N + col);
                v0 += p0.x * pr0; v1 += p0.y * pr0;
                v2 += p1.x * pr1; v3 += p1.y * pr1;
            }
            if (outF) {
                *(float2*)(outF + (size_t)r * N + col)       = make_float2(v0, v1);
                *(float2*)(outF + (size_t)(r + 8) * N + col) = make_float2(v2, v3);
            }
            if (outH) {
                union { __half b[2]; uint32_t u; } h0, l0, h1, l1;
                hsplit(v0 * oscale, h0.b[0], l0.b[0]); hsplit(v1 * oscale, h0.b[1], l0.b[1]);
                hsplit(v2 * oscale, h1.b[0], l1.b[0]); hsplit(v3 * oscale, h1.b[1], l1.b[1]);
                *(uint32_t*)(outH + (size_t)r * N + col)       = h0.u;
                *(uint32_t*)(outL + (size_t)r * N + col)       = l0.u;
                *(uint32_t*)(outH + (size_t)(r + 8) * N + col) = h1.u;
                *(uint32_t*)(outL + (size_t)(r + 8) * N + col) = l1.u;
            }
        }
    }
}

// ---------------------------------------------------------------------------
// Weight / input conversion kernels (fp16 hi/lo with scale)
// ---------------------------------------------------------------------------
__global__ __launch_bounds__(256)
void conv_split(const float* __restrict__ in,
                __half* __restrict__ hi, __half* __restrict__ lo, float scale)
{
    int i = blockIdx.x * 256 + threadIdx.x;
    float4 v = ((const float4*)in)[i];
    union { __half b[4]; uint2 u; } uh, ul;
    hsplit(v.x * scale, uh.b[0], ul.b[0]);
    hsplit(v.y * scale, uh.b[1], ul.b[1]);
    hsplit(v.z * scale, uh.b[2], ul.b[2]);
    hsplit(v.w * scale, uh.b[3], ul.b[3]);
    ((uint2*)hi)[i] = uh.u;
    ((uint2*)lo)[i] = ul.u;
}

__global__ __launch_bounds__(256)
void conv_trans(const float* __restrict__ D,
                __half* __restrict__ th, __half* __restrict__ tl, float scale)
{
    __shared__ float t[32][33];
    const int n0 = blockIdx.x * 32, k0 = blockIdx.y * 32;
    const int tx = threadIdx.x & 31, ty = threadIdx.x >> 5;
    #pragma unroll
    for (int j = 0; j < 32; j += 8)
        t[ty + j][tx] = D[(size_t)(k0 + ty + j) * CDIN + n0 + tx];
    __syncthreads();
    #pragma unroll
    for (int j = 0; j < 32; j += 8) {
        float v = t[tx][ty + j] * scale;
        __half h, l; hsplit(v, h, l);
        th[(size_t)(n0 + ty + j) * CW + k0 + tx] = h;
        tl[(size_t)(n0 + ty + j) * CW + k0 + tx] = l;
    }
}

__global__ __launch_bounds__(256)
void subb_kernel(const float* __restrict__ xin, const float* __restrict__ b,
                 float* __restrict__ X,
                 __half* __restrict__ Xh, __half* __restrict__ Xl)
{
    int i = blockIdx.x * 256 + threadIdx.x;
    float4 v = ((const float4*)xin)[i];
    int col = (i * 4) & (CDIN - 1);
    float4 bb = *(const float4*)(b + col);
    v.x -= bb.x; v.y -= bb.y; v.z -= bb.z; v.w -= bb.w;
    ((float4*)X)[i] = v;
    union { __half b[4]; uint2 u; } uh, ul;
    hsplit(v.x, uh.b[0], ul.b[0]);
    hsplit(v.y, uh.b[1], ul.b[1]);
    hsplit(v.z, uh.b[2], ul.b[2]);
    hsplit(v.w, uh.b[3], ul.b[3]);
    ((uint2*)Xh)[i] = uh.u;
    ((uint2*)Xl)[i] = ul.u;
}

// ---------------------------------------------------------------------------
// Causal attention: fp32 scores/softmax, tensor-core P@V (3-pass fp16 hi/lo).
// Block = 64 q-rows x 256 dv (dvt in {0,1}), 256 threads, 8 warps (4q x 2dv).
// qt REVERSED: heavy (large-qt) blocks dispatch first -> light tail wave.
// ---------------------------------------------------------------------------
__global__ __launch_bounds__(256)
void attn_kernel(const float* __restrict__ Q, const float* __restrict__ Kt,
                 const __half* __restrict__ Vh, const __half* __restrict__ Vl,
                 __half* __restrict__ Oh, __half* __restrict__ Ol)
{
    __shared__ float qs[64][8];
    __shared__ float ks[32][8];
    __shared__ __align__(16) __half pH[64][40];    // 80B row stride
    __shared__ __align__(16) __half pL[64][40];
    __shared__ __align__(16) __half vsh[32][264];  // 528B row stride
    __shared__ __align__(16) __half vsl[32][264];
    __shared__ float rowM[64], rowL[64], rowF[64];

    const int tid = threadIdx.x;
    const int dvt = blockIdx.x;          // 0..1 (256 dv each)
    const int qt  = (int)(gridDim.y - 1 - blockIdx.y);   // reversed: heavy first
    const int bh  = blockIdx.z;          // 0..31
    const int bb  = bh >> 3, h = bh & 7;
    const int qBase = qt * 64;

    #pragma unroll
    for (int i = 0; i < 2; i++) {
        int idx = tid + i * 256;
        qs[idx >> 3][idx & 7] =
            Q[(size_t)(bb * CL + qBase + (idx >> 3)) * CNE + h * CDH + (idx & 7)];
    }
    if (tid < 64) { rowM[tid] = -INFINITY; rowL[tid] = 0.f; }

    const int l   = tid & 31, wid = tid >> 5;
    const int wq  = (wid >> 1) * 16;     // 0,16,32,48
    const int wd  = (wid & 1) * 128;     // 0,128

    float acc[16][4];
    #pragma unroll
    for (int nf = 0; nf < 16; nf++)
        #pragma unroll
        for (int q = 0; q < 4; q++) acc[nf][q] = 0.f;

    const int sr = tid >> 2, sg = tid & 3;

    const uint32_t pH0 = smem_u32(pH), pL0 = smem_u32(pL);
    const uint32_t vh0 = smem_u32(vsh), vl0 = smem_u32(vsl);
    const uint32_t aOff  = (uint32_t)(wq + (l & 15)) * 80 + ((l & 16) ? 16u : 0u);
    const uint32_t vRow  = (uint32_t)(l & 15);
    const uint32_t vCol8 = (uint32_t)(l >> 4) * 8;

    const int nst = qt * 2 + 2;
    for (int st = 0; st < nst; st++) {
        const int s0 = st * 32;
        __syncthreads();
        ks[tid >> 3][tid & 7] =
            Kt[(size_t)(bb * CL + s0 + (tid >> 3)) * CNE + h * CDH + (tid & 7)];
        // V tile: 32 rows x 256 halves, hi+lo
        #pragma unroll
        for (int i = 0; i < 4; i++) {
            int idx = tid + i * 256;             // 0..1023
            int r = idx >> 5, c8 = (idx & 31) * 8;
            size_t g = (size_t)(bb * CL + s0 + r) * CW + h * CDV + dvt * 256 + c8;
            *(uint4*)&vsh[r][c8] = *(const uint4*)(Vh + g);
            *(uint4*)&vsl[r][c8] = *(const uint4*)(Vl + g);
        }
        __syncthreads();

        // scores + online softmax: thread (sr, sg) owns row sr, s = sg*8..+7
        {
            float qv[8];
            #pragma unroll
            for (int d = 0; d < 8; d++) qv[d] = qs[sr][d];
            const int lglob = qBase + sr;
            float sc[8];
            #pragma unroll
            for (int i = 0; i < 8; i++) {
                int s = sg * 8 + i;
                float dot = 0.f;
                #pragma unroll
                for (int d = 0; d < 8; d++) dot += qv[d] * ks[s][d];
                sc[i] = (s0 + s <= lglob) ? dot * SCALE_LOG2E : -INFINITY;
            }
            float mt = sc[0];
            #pragma unroll
            for (int i = 1; i < 8; i++) mt = fmaxf(mt, sc[i]);
            mt = fmaxf(mt, __shfl_xor_sync(0xffffffffu, mt, 1));
            mt = fmaxf(mt, __shfl_xor_sync(0xffffffffu, mt, 2));
            const float mold = rowM[sr];
            const float mnew = fmaxf(mold, mt);
            float p[8], lsum = 0.f;
            #pragma unroll
            for (int i = 0; i < 8; i++) { p[i] = ex2f(sc[i] - mnew); lsum += p[i]; }
            lsum += __shfl_xor_sync(0xffffffffu, lsum, 1);
            lsum += __shfl_xor_sync(0xffffffffu, lsum, 2);
            if (sg == 0) {
                float f = ex2f(mold - mnew);
                rowF[sr] = f;
                rowL[sr] = rowL[sr] * f + lsum;
                rowM[sr] = mnew;
            }
            union { __half b[8]; uint4 u; } uh, ul;
            #pragma unroll
            for (int i = 0; i < 8; i++) hsplit(p[i], uh.b[i], ul.b[i]);
            *(uint4*)&pH[sr][sg * 8] = uh.u;
            *(uint4*)&pL[sr][sg * 8] = ul.u;
        }
        __syncthreads();

        // rescale accumulators
        const float f0 = rowF[wq + (l >> 2)], f1 = rowF[wq + 8 + (l >> 2)];
        #pragma unroll
        for (int nf = 0; nf < 16; nf++) {
            acc[nf][0] *= f0; acc[nf][1] *= f0;
            acc[nf][2] *= f1; acc[nf][3] *= f1;
        }

        // P fragments (hi/lo, 2 k16-steps)
        uint32_t aH[2][4], aL[2][4];
        ldm_x4(aH[0], pH0 + aOff);
        ldm_x4(aH[1], pH0 + aOff + 32);
        ldm_x4(aL[0], pL0 + aOff);
        ldm_x4(aL[1], pL0 + aOff + 32);

        #pragma unroll
        for (int kk = 0; kk < 2; kk++) {
            #pragma unroll
            for (int nb = 0; nb < 8; nb++) {
                uint32_t ad = (uint32_t)((kk * 16 + vRow) * 528)
                            + (uint32_t)((wd + nb * 16) + vCol8) * 2;
                uint32_t bv[4], blo[4];
                ldm_x4_trans(bv,  vh0 + ad);
                ldm_x4_trans(blo, vl0 + ad);
                mma16816(acc[2 * nb],     aH[kk], &bv[0]);
                mma16816(acc[2 * nb + 1], aH[kk], &bv[2]);
                mma16816(acc[2 * nb],     aL[kk], &bv[0]);
                mma16816(acc[2 * nb + 1], aL[kk], &bv[2]);
                mma16816(acc[2 * nb],     aH[kk], &blo[0]);
                mma16816(acc[2 * nb + 1], aH[kk], &blo[2]);
            }
        }
    }

    // epilogue: O_scaled = acc / rowL (acc already carries x4096 via V)
    const int r0 = wq + (l >> 2);
    const float inv0 = 1.f / rowL[r0], inv1 = 1.f / rowL[r0 + 8];
    #pragma unroll
    for (int nf = 0; nf < 16; nf++) {
        int col = h * CDV + dvt * 256 + wd + nf * 8 + 2 * (l & 3);
        size_t g0 = (size_t)(bb * CL + qBase + r0) * CW + col;
        size_t g1 = (size_t)(bb * CL + qBase + r0 + 8) * CW + col;
        union { __half b[2]; uint32_t u; } h0, l0_, h1, l1_;
        hsplit(acc[nf][0] * inv0, h0.b[0], l0_.b[0]);
        hsplit(acc[nf][1] * inv0, h0.b[1], l0_.b[1]);
        hsplit(acc[nf][2] * inv1, h1.b[0], l1_.b[0]);
        hsplit(acc[nf][3] * inv1, h1.b[1], l1_.b[1]);
        *(uint32_t*)(Oh + g0) = h0.u; *(uint32_t*)(Ol + g0) = l0_.u;
        *(uint32_t*)(Oh + g1) = h1.u; *(uint32_t*)(Ol + g1) = l1_.u;
    }
}

// ---------------------------------------------------------------------------
// proj = <Dz,x>/(||Dz||+eps)^2 ; x2 = x - proj*Dz -> fp16 hi/lo (scale 1)
// ---------------------------------------------------------------------------
__global__ __launch_bounds__(256)
void proj_kernel(const float* __restrict__ DZ, const float* __restrict__ X,
                 float* __restrict__ proj,
                 __half* __restrict__ Xh, __half* __restrict__ Xl)
{
    __shared__ float sn[8], sd[8], s_ps;
    const int m = blockIdx.x;
    const int tid = threadIdx.x;
    const float* dz = DZ + (size_t)m * CDIN;
    const float* x  = X  + (size_t)m * CDIN;

    float dzv[2], xv[2];
    float n2 = 0.f, dt = 0.f;
    #pragma unroll
    for (int i = 0; i < 2; i++) {
        int c = tid + i * 256;
        dzv[i] = dz[c];
        xv[i]  = x[c];
        n2 += dzv[i] * dzv[i];
        dt += dzv[i] * xv[i];
    }
    #pragma unroll
    for (int o = 16; o; o >>= 1) {
        n2 += __shfl_xor_sync(0xffffffffu, n2, o);
        dt += __shfl_xor_sync(0xffffffffu, dt, o);
    }
    int w = tid >> 5;
    if ((tid & 31) == 0) { sn[w] = n2; sd[w] = dt; }
    __syncthreads();
    if (tid == 0) {
        float N2 = 0.f, DT = 0.f;
        #pragma unroll
        for (int i = 0; i < 8; i++) { N2 += sn[i]; DT += sd[i]; }
        float nrm = sqrtf(N2) + 1e-6f;
        float ps  = DT / (nrm * nrm);
        s_ps = ps;
        proj[m] = ps;
    }
    __syncthreads();
    float ps = s_ps;
    #pragma unroll
    for (int i = 0; i < 2; i++) {
        int c = tid + i * 256;
        float v = xv[i] - ps * dzv[i];
        __half h, l; hsplit(v, h, l);
        Xh[(size_t)m * CDIN + c] = h;
        Xl[(size_t)m * CDIN + c] = l;
    }
}

// ---------------------------------------------------------------------------
// launch  (ordered so ncu -s 5 -c 1 profiles the big v-GEMM)
// ---------------------------------------------------------------------------
extern "C" void kernel_launch(void* const* d_in, const int* in_sizes, int n_in,
                              void* d_out, int out_size)
{
    const float* x_input = (const float*)d_in[0];
    const float* D    = (const float*)d_in[1];
    const float* b    = (const float*)d_in[2];
    const float* k_w  = (const float*)d_in[3];
    const float* k_b  = (const float*)d_in[4];
    const float* q_w  = (const float*)d_in[5];
    const float* q_b  = (const float*)d_in[6];
    const float* v_w  = (const float*)d_in[7];
    const float* v_b  = (const float*)d_in[8];
    const float* o_w  = (const float*)d_in[9];
    const float* o_b  = (const float*)d_in[10];
    float* out = (float*)d_out;

    float *X, *P, *Q, *K, *DZ, *PRJ;
    __half *Xh, *Xl, *Zh, *Zl, *Vh, *Vl, *Oh, *Ol, *Ph, *Pl;
    __half *Dwh, *Dwl, *Dth, *Dtl, *vwh, *vwl, *owh, *owl, *qwh, *qwl, *kwh, *kwl;
    cudaGetSymbolAddress((void**)&X,  g_X);
    cudaGetSymbolAddress((void**)&P,  g_P);
    cudaGetSymbolAddress((void**)&Q,  g_Q);
    cudaGetSymbolAddress((void**)&K,  g_K);
    cudaGetSymbolAddress((void**)&DZ, g_DZ);
    cudaGetSymbolAddress((void**)&PRJ, g_PRJ);
    cudaGetSymbolAddress((void**)&Xh, g_Xh); cudaGetSymbolAddress((void**)&Xl, g_Xl);
    cudaGetSymbolAddress((void**)&Zh, g_Zh); cudaGetSymbolAddress((void**)&Zl, g_Zl);
    cudaGetSymbolAddress((void**)&Vh, g_Vh); cudaGetSymbolAddress((void**)&Vl, g_Vl);
    cudaGetSymbolAddress((void**)&Oh, g_Oh); cudaGetSymbolAddress((void**)&Ol, g_Ol);
    cudaGetSymbolAddress((void**)&Ph, g_Ph); cudaGetSymbolAddress((void**)&Pl, g_Pl);
    cudaGetSymbolAddress((void**)&Dwh, g_Dwh); cudaGetSymbolAddress((void**)&Dwl, g_Dwl);
    cudaGetSymbolAddress((void**)&Dth, g_Dth); cudaGetSymbolAddress((void**)&Dtl, g_Dtl);
    cudaGetSymbolAddress((void**)&vwh, g_vwh); cudaGetSymbolAddress((void**)&vwl, g_vwl);
    cudaGetSymbolAddress((void**)&owh, g_owh); cudaGetSymbolAddress((void**)&owl, g_owl);
    cudaGetSymbolAddress((void**)&qwh, g_qwh); cudaGetSymbolAddress((void**)&qwl, g_qwl);
    cudaGetSymbolAddress((void**)&kwh, g_kwh); cudaGetSymbolAddress((void**)&kwl, g_kwl);

    const int SM_B1   = 3 * (1 * 256 * 144 + 1 * 128 * 144);   // <256,128,1> 3-stage: 165888
    const int SM_B3   = 2 * (2 * 256 * 144 + 2 * 128 * 144);   // <256,128,3> 2-stage: 221184
    const int SM_N64  = 3 * (2 * 128 * 144 + 2 * 64 * 144);    // <128,64,3>  3-stage: 165888
    cudaFuncSetAttribute(mma_gemm<256, 128, 1>, cudaFuncAttributeMaxDynamicSharedMemorySize, SM_B1);
    cudaFuncSetAttribute(mma_gemm<256, 128, 3>, cudaFuncAttributeMaxDynamicSharedMemorySize, SM_B3);
    cudaFuncSetAttribute(mma_gemm<128, 64, 3>,  cudaFuncAttributeMaxDynamicSharedMemorySize, SM_N64);

    const float lam = 1.0f / (4.0f * CDIN);
    const float iAW = 1.0f / (S_ACT * S_WT);   // 2^-20, exact
    dim3 blk(256);

    // [0] [1] D conversions, [2] subb
    conv_split<<<(CW * CDIN) / 1024, blk>>>(D, Dwh, Dwl, S_WT);
    conv_trans<<<dim3(CDIN / 32, CW / 32), blk>>>(D, Dth, Dtl, S_WT);
    subb_kernel<<<(CM * CDIN) / 1024, blk>>>(x_input, b, X, Xh, Xl);

    // [3] z_input = relu(lam * x @ D^T)   (BM=256, 512 threads, 3-pass)
    mma_gemm<256, 128, 3><<<dim3(CW / 128, CM / 256), 512, SM_B3>>>(
        Xh, Xl, Dwh, Dwl, nullptr, nullptr, CDIN, CW, 0, 0,
        lam / S_WT, nullptr, nullptr, 1, nullptr, nullptr,
        nullptr, nullptr, Zh, Zl, S_ACT);

    // [4] v_w conversion, [5] v GEMM (ncu target) -> Vh/Vl (x4096), 1-pass
    conv_split<<<(CW * CW) / 1024, blk>>>(v_w, vwh, vwl, S_WT);
    mma_gemm<256, 128, 1><<<dim3(CW / 128, CM / 256), 512, SM_B1>>>(
        Zh, Zl, vwh, vwl, nullptr, nullptr, CW, CW, 1, 0,
        iAW, v_b, nullptr, 0, nullptr, nullptr,
        nullptr, nullptr, Vh, Vl, S_ACT);

    // [6] [7] q/k conversions, [8] fused q&k GEMM (3-pass)
    conv_split<<<(CNE * CW) / 1024, blk>>>(q_w, qwh, qwl, S_WT);
    conv_split<<<(CNE * CW) / 1024, blk>>>(k_w, kwh, kwl, S_WT);
    mma_gemm<128, 64, 3><<<dim3(2, CM / 128), 256, SM_N64>>>(
        Zh, Zl, qwh, qwl, kwh, kwl, CW, CNE, 0, 1,
        iAW, q_b, k_b, 0, nullptr, nullptr,
        Q, K, nullptr, nullptr, 1.f);

    // [9] attention (tensor-core P@V, heavy-first scheduling)
    attn_kernel<<<dim3(2, CL / 64, CB * CH), blk>>>(Q, K, Vh, Vl, Oh, Ol);

    // [10] o_w conversion, [11] z_pred_ = relu(o @ o_w^T + o_b), 1-pass
    conv_split<<<(CW * CW) / 1024, blk>>>(o_w, owh, owl, S_WT);
    mma_gemm<256, 128, 1><<<dim3(CW / 128, CM / 256), 512, SM_B1>>>(
        Oh, Ol, owh, owl, nullptr, nullptr, CW, CW, 0, 0,
        iAW, o_b, nullptr, 1, nullptr, nullptr,
        P, nullptr, Ph, Pl, S_ACT);

    // [12] Dz = z_pred_ @ D   (BM=256, 3-pass, single-wave 128 blocks)
    mma_gemm<256, 128, 3><<<dim3(CDIN / 128, CM / 256), 512, SM_B3>>>(
        Ph, Pl, Dth, Dtl, nullptr, nullptr, CW, CDIN, 0, 0,
        iAW, nullptr, nullptr, 0, nullptr, nullptr,
        DZ, nullptr, nullptr, nullptr, 1.f);

    // [13] proj scale + x2
    proj_kernel<<<CM, blk>>>(DZ, X, PRJ, Xh, Xl);

    // [14] z_sum = relu(lam * x2 @ D^T) + z_pred_ * proj  (BM=256, 3-pass)
    mma_gemm<256, 128, 3><<<dim3(CW / 128, CM / 256), 512, SM_B3>>>(
        Xh, Xl, Dwh, Dwl, nullptr, nullptr, CDIN, CW, 0, 0,
        lam / S_WT, nullptr, nullptr, 1, P, PRJ,
        nullptr, nullptr, Zh, Zl, S_ACT);

    // [15] x_recons = z_sum @ D + b   (BM=256, 3-pass)
    mma_gemm<256, 128, 3><<<dim3(CDIN / 128, CM / 256), 512, SM_B3>>>(
        Zh, Zl, Dth, Dtl, nullptr, nullptr, CW, CDIN, 0, 0,
        iAW, b, nullptr, 0, nullptr, nullptr,
        out, nullptr, nullptr, nullptr, 1.f);
}